// round 1
// baseline (speedup 1.0000x reference)
#include <cuda_runtime.h>
#include <math.h>

// Problem constants
#define BSZ   4
#define CCH   256
#define HIDD  128
#define NPIX  4096   // 64*64

// GEMM tiling
#define BK  16
#define BMT 128
#define BNT 128
#define TM  8
#define TN  8
#define NTHREADS 256

// ---------------- scratch (static device globals; no runtime allocation) ---
__device__ float g_qkv[(size_t)3 * BSZ * HIDD * NPIX];        // 25 MB: phi|theta|g
__device__ float g_S[(size_t)BSZ * NPIX * NPIX];              // 256 MB scores
__device__ float g_pmax[BSZ * 16 * NPIX];
__device__ float g_psum[BSZ * 16 * NPIX];
__device__ float g_cmax[BSZ * NPIX];
__device__ float g_cinv[BSZ * NPIX];
__device__ float g_ag[(size_t)BSZ * HIDD * NPIX];             // 8 MB attn_g [b][c][n]

// ---------------- shared micro-kernel: 128x128x16 tile, 8x8 per thread -----
__device__ __forceinline__ void mm_tile(const float (*As)[BMT],
                                        const float (*Bs)[BNT],
                                        float acc[TM][TN], int tx, int ty) {
#pragma unroll
    for (int k = 0; k < BK; ++k) {
        float4 a0 = *(const float4*)(&As[k][ty * TM]);
        float4 a1 = *(const float4*)(&As[k][ty * TM + 4]);
        float4 b0 = *(const float4*)(&Bs[k][tx * TN]);
        float4 b1 = *(const float4*)(&Bs[k][tx * TN + 4]);
        float av[TM] = {a0.x, a0.y, a0.z, a0.w, a1.x, a1.y, a1.z, a1.w};
        float bv[TN] = {b0.x, b0.y, b0.z, b0.w, b1.x, b1.y, b1.z, b1.w};
#pragma unroll
        for (int i = 0; i < TM; ++i)
#pragma unroll
            for (int j = 0; j < TN; ++j)
                acc[i][j] = fmaf(av[i], bv[j], acc[i][j]);
    }
}

// K1: qkv projection. out[b][o][n] = sum_c W[o][c] * x[b][c][n]
// grid (NPIX/BNT=32, 1, BSZ); slab selects phi/theta/g output region.
__global__ __launch_bounds__(NTHREADS)
void k_qkv(const float* __restrict__ W, const float* __restrict__ x, int slab) {
    __shared__ float As[BK][BMT];
    __shared__ float Bs[BK][BNT];
    int b  = blockIdx.z;
    int n0 = blockIdx.x * BNT;
    int tid = threadIdx.x, tx = tid & 15, ty = tid >> 4;
    const float* xb = x + (size_t)b * CCH * NPIX;
    float* ob = g_qkv + ((size_t)slab * BSZ + b) * HIDD * NPIX;
    float acc[TM][TN] = {};
    for (int k0 = 0; k0 < CCH; k0 += BK) {
#pragma unroll
        for (int e = tid; e < BMT * BK; e += NTHREADS) {
            int ml = e >> 4, kl = e & 15;                 // HID==BMT, m0==0
            As[kl][ml] = W[ml * CCH + k0 + kl];
        }
#pragma unroll
        for (int e = tid; e < BK * BNT; e += NTHREADS) {
            int kl = e >> 7, nl = e & 127;
            Bs[kl][nl] = xb[(size_t)(k0 + kl) * NPIX + n0 + nl];
        }
        __syncthreads();
        mm_tile(As, Bs, acc, tx, ty);
        __syncthreads();
    }
#pragma unroll
    for (int i = 0; i < TM; ++i) {
        float* orow = ob + (size_t)(ty * TM + i) * NPIX + n0 + tx * TN;
        *(float4*)orow       = make_float4(acc[i][0], acc[i][1], acc[i][2], acc[i][3]);
        *(float4*)(orow + 4) = make_float4(acc[i][4], acc[i][5], acc[i][6], acc[i][7]);
    }
}

// K2: S[b][n][m] = sum_c theta[b][c][n] * phi[b][c][m].  grid (32,32,BSZ)
__global__ __launch_bounds__(NTHREADS)
void k_scores() {
    __shared__ float As[BK][BMT];
    __shared__ float Bs[BK][BNT];
    int b  = blockIdx.z;
    int n0 = blockIdx.y * BMT;
    int m0 = blockIdx.x * BNT;
    int tid = threadIdx.x, tx = tid & 15, ty = tid >> 4;
    const float* ph = g_qkv + (size_t)(0 * BSZ + b) * HIDD * NPIX;
    const float* th = g_qkv + (size_t)(1 * BSZ + b) * HIDD * NPIX;
    float* Sb = g_S + (size_t)b * NPIX * NPIX;
    float acc[TM][TN] = {};
    for (int k0 = 0; k0 < HIDD; k0 += BK) {
#pragma unroll
        for (int e = tid; e < BK * BMT; e += NTHREADS) {
            int kl = e >> 7, nl = e & 127;
            As[kl][nl] = th[(size_t)(k0 + kl) * NPIX + n0 + nl];
        }
#pragma unroll
        for (int e = tid; e < BK * BNT; e += NTHREADS) {
            int kl = e >> 7, ml = e & 127;
            Bs[kl][ml] = ph[(size_t)(k0 + kl) * NPIX + m0 + ml];
        }
        __syncthreads();
        mm_tile(As, Bs, acc, tx, ty);
        __syncthreads();
    }
#pragma unroll
    for (int i = 0; i < TM; ++i) {
        float* srow = Sb + (size_t)(n0 + ty * TM + i) * NPIX + m0 + tx * TN;
        *(float4*)srow       = make_float4(acc[i][0], acc[i][1], acc[i][2], acc[i][3]);
        *(float4*)(srow + 4) = make_float4(acc[i][4], acc[i][5], acc[i][6], acc[i][7]);
    }
}

// K3a: partial column (axis-n) online softmax stats. grid (16,16,BSZ), 256 thr.
__global__ void k_colstats() {
    int b  = blockIdx.z;
    int m  = blockIdx.x * 256 + threadIdx.x;
    int nc = blockIdx.y;
    const float* Sb = g_S + (size_t)b * NPIX * NPIX;
    float mx = -3.4e38f, sm = 0.f;
    int nbeg = nc * (NPIX / 16);
#pragma unroll 4
    for (int n = nbeg; n < nbeg + NPIX / 16; ++n) {
        float v = Sb[(size_t)n * NPIX + m];
        if (v > mx) { sm = sm * __expf(mx - v) + 1.f; mx = v; }
        else        { sm += __expf(v - mx); }
    }
    g_pmax[(b * 16 + nc) * NPIX + m] = mx;
    g_psum[(b * 16 + nc) * NPIX + m] = sm;
}

// K3b: combine the 16 partials -> colmax, 1/colsum. grid 64 x 256 thr.
__global__ void k_combine() {
    int idx = blockIdx.x * 256 + threadIdx.x;   // idx = b*NPIX + m
    int b = idx >> 12, m = idx & 4095;
    float M = -3.4e38f;
#pragma unroll
    for (int c = 0; c < 16; ++c)
        M = fmaxf(M, g_pmax[(b * 16 + c) * NPIX + m]);
    float s = 0.f;
#pragma unroll
    for (int c = 0; c < 16; ++c)
        s += g_psum[(b * 16 + c) * NPIX + m] * __expf(g_pmax[(b * 16 + c) * NPIX + m] - M);
    g_cmax[idx] = M;
    g_cinv[idx] = 1.f / s;
}

// K4: attn_g[b][c][n] = sum_m P[n][m] * g[b][c][m], P = exp(S-colmax)*colinv.
// M-dim=n (4096), N-dim=c (128 = one BNT tile), K-dim=m (4096). grid (1,32,BSZ)
__global__ __launch_bounds__(NTHREADS)
void k_attng() {
    __shared__ float As[BK][BMT];
    __shared__ float Bs[BK][BNT];
    int b  = blockIdx.z;
    int n0 = blockIdx.y * BMT;
    int tid = threadIdx.x, tx = tid & 15, ty = tid >> 4;
    const float* Sb = g_S + (size_t)b * NPIX * NPIX;
    const float* gb = g_qkv + (size_t)(2 * BSZ + b) * HIDD * NPIX;
    const float* cm = g_cmax + b * NPIX;
    const float* ci = g_cinv + b * NPIX;
    float* agb = g_ag + (size_t)b * HIDD * NPIX;
    float acc[TM][TN] = {};
    for (int k0 = 0; k0 < NPIX; k0 += BK) {
#pragma unroll
        for (int e = tid; e < BMT * BK; e += NTHREADS) {
            int nl = e >> 4, kl = e & 15;
            int m = k0 + kl;
            float s = Sb[(size_t)(n0 + nl) * NPIX + m];
            As[kl][nl] = __expf(s - cm[m]) * ci[m];
        }
#pragma unroll
        for (int e = tid; e < BK * BNT; e += NTHREADS) {
            int cl = e >> 4, kl = e & 15;
            Bs[kl][cl] = gb[(size_t)cl * NPIX + k0 + kl];
        }
        __syncthreads();
        mm_tile(As, Bs, acc, tx, ty);
        __syncthreads();
    }
    // transposed write into [c][n]
#pragma unroll
    for (int i = 0; i < TM; ++i)
#pragma unroll
        for (int j = 0; j < TN; ++j)
            agb[(size_t)(tx * TN + j) * NPIX + n0 + ty * TM + i] = acc[i][j];
}

// K5: out[b][co][n] = x[...] + sum_h w_mask[co][h] * attn_g[b][h][n]. grid (32,2,BSZ)
__global__ __launch_bounds__(NTHREADS)
void k_mask(const float* __restrict__ wm, const float* __restrict__ x,
            float* __restrict__ out) {
    __shared__ float As[BK][BMT];
    __shared__ float Bs[BK][BNT];
    int b  = blockIdx.z;
    int n0 = blockIdx.x * BNT;
    int m0 = blockIdx.y * BMT;
    int tid = threadIdx.x, tx = tid & 15, ty = tid >> 4;
    const float* agb = g_ag + (size_t)b * HIDD * NPIX;
    float acc[TM][TN] = {};
    for (int k0 = 0; k0 < HIDD; k0 += BK) {
#pragma unroll
        for (int e = tid; e < BMT * BK; e += NTHREADS) {
            int ml = e >> 4, kl = e & 15;
            As[kl][ml] = wm[(m0 + ml) * HIDD + k0 + kl];
        }
#pragma unroll
        for (int e = tid; e < BK * BNT; e += NTHREADS) {
            int kl = e >> 7, nl = e & 127;
            Bs[kl][nl] = agb[(size_t)(k0 + kl) * NPIX + n0 + nl];
        }
        __syncthreads();
        mm_tile(As, Bs, acc, tx, ty);
        __syncthreads();
    }
#pragma unroll
    for (int i = 0; i < TM; ++i) {
        size_t base = (size_t)b * CCH * NPIX + (size_t)(m0 + ty * TM + i) * NPIX + n0 + tx * TN;
        float4 x0 = *(const float4*)(x + base);
        float4 x1 = *(const float4*)(x + base + 4);
        *(float4*)(out + base)     = make_float4(acc[i][0] + x0.x, acc[i][1] + x0.y,
                                                 acc[i][2] + x0.z, acc[i][3] + x0.w);
        *(float4*)(out + base + 4) = make_float4(acc[i][4] + x1.x, acc[i][5] + x1.y,
                                                 acc[i][6] + x1.z, acc[i][7] + x1.w);
    }
}

extern "C" void kernel_launch(void* const* d_in, const int* in_sizes, int n_in,
                              void* d_out, int out_size) {
    const float* x       = (const float*)d_in[0];
    const float* w_phi   = (const float*)d_in[1];
    const float* w_theta = (const float*)d_in[2];
    const float* w_g     = (const float*)d_in[3];
    const float* w_mask  = (const float*)d_in[4];
    float* out = (float*)d_out;
    (void)in_sizes; (void)n_in; (void)out_size;

    dim3 blk(NTHREADS);
    k_qkv<<<dim3(NPIX / BNT, 1, BSZ), blk>>>(w_phi,   x, 0);
    k_qkv<<<dim3(NPIX / BNT, 1, BSZ), blk>>>(w_theta, x, 1);
    k_qkv<<<dim3(NPIX / BNT, 1, BSZ), blk>>>(w_g,     x, 2);
    k_scores<<<dim3(NPIX / BNT, NPIX / BMT, BSZ), blk>>>();
    k_colstats<<<dim3(NPIX / 256, 16, BSZ), blk>>>();
    k_combine<<<dim3(BSZ * NPIX / 256), blk>>>();
    k_attng<<<dim3(1, NPIX / BMT, BSZ), blk>>>();
    k_mask<<<dim3(NPIX / BNT, CCH / BMT, BSZ), blk>>>(w_mask, x, out);
}

// round 3
// speedup vs baseline: 6.2290x; 6.2290x over previous
#include <cuda_runtime.h>
#include <cuda_fp16.h>
#include <math.h>
#include <stdint.h>

#define BSZ   4
#define CCH   256
#define HIDD  128
#define NPIX  4096

// ---------------- scratch (static device globals) --------------------------
__device__ __half g_xt [(size_t)BSZ * NPIX * CCH];    // x^T  [b][n][c] fp16
__device__ __half g_tht[(size_t)BSZ * NPIX * HIDD];   // theta^T [b][n][c]
__device__ __half g_phi[(size_t)BSZ * NPIX * HIDD];   // phi^T   [b][m][c]
__device__ __half g_gh [(size_t)BSZ * HIDD * NPIX];   // g       [b][c][m]
__device__ __half g_agt[(size_t)BSZ * NPIX * HIDD];   // attn_g^T [b][n][c]
__device__ __half g_S16[(size_t)BSZ * NPIX * NPIX];   // scores fp16 (128 MB)
__device__ __half g_whp[HIDD * CCH];
__device__ __half g_wht[HIDD * CCH];
__device__ __half g_whg[HIDD * CCH];
__device__ __half g_whm[CCH * HIDD];
__device__ float  g_pmax[BSZ * 16 * NPIX];
__device__ float  g_psum[BSZ * 16 * NPIX];
__device__ float  g_cmax[BSZ * NPIX];
__device__ float  g_cinv[BSZ * NPIX];

// ---------------- PTX helpers ----------------------------------------------
__device__ __forceinline__ uint32_t s2u(const void* p) {
    return (uint32_t)__cvta_generic_to_shared(p);
}
#define CP16(dst, src) \
    asm volatile("cp.async.cg.shared.global [%0], [%1], 16;" :: "r"(dst), "l"(src))
#define CP_COMMIT() asm volatile("cp.async.commit_group;" ::: "memory")
#define CP_WAIT1()  asm volatile("cp.async.wait_group 1;" ::: "memory")
#define CP_WAIT0()  asm volatile("cp.async.wait_group 0;" ::: "memory")

__device__ __forceinline__ void ldsm_x4(uint32_t& r0, uint32_t& r1,
                                        uint32_t& r2, uint32_t& r3, uint32_t a) {
    asm volatile("ldmatrix.sync.aligned.m8n8.x4.shared.b16 {%0,%1,%2,%3}, [%4];"
                 : "=r"(r0), "=r"(r1), "=r"(r2), "=r"(r3) : "r"(a));
}
__device__ __forceinline__ void mma16816(float* d, const uint32_t* a,
                                         uint32_t b0, uint32_t b1) {
    asm volatile(
        "mma.sync.aligned.m16n8k16.row.col.f32.f16.f16.f32 "
        "{%0,%1,%2,%3}, {%4,%5,%6,%7}, {%8,%9}, {%0,%1,%2,%3};"
        : "+f"(d[0]), "+f"(d[1]), "+f"(d[2]), "+f"(d[3])
        : "r"(a[0]), "r"(a[1]), "r"(a[2]), "r"(a[3]), "r"(b0), "r"(b1));
}

#define SMS 40   // smem row stride in halves (32 data + 8 pad) -> 80B rows

// Shared mainloop compute step (one 32-wide K chunk)
#define MMA_CHUNK(as, bs)                                                     \
    do {                                                                      \
        _Pragma("unroll")                                                     \
        for (int kk = 0; kk < 2; ++kk) {                                      \
            uint32_t afr[4][4], bfr[2][4];                                    \
            _Pragma("unroll")                                                 \
            for (int fm = 0; fm < 4; ++fm) {                                  \
                uint32_t ad = s2u(&(as)[(wm + fm * 16 + (lane & 15)) * SMS +  \
                                        kk * 16 + (lane >> 4) * 8]);          \
                ldsm_x4(afr[fm][0], afr[fm][1], afr[fm][2], afr[fm][3], ad);  \
            }                                                                 \
            _Pragma("unroll")                                                 \
            for (int fp = 0; fp < 2; ++fp) {                                  \
                uint32_t bd = s2u(&(bs)[(wn + fp * 16 + (lane & 15)) * SMS +  \
                                        kk * 16 + (lane >> 4) * 8]);          \
                ldsm_x4(bfr[fp][0], bfr[fp][1], bfr[fp][2], bfr[fp][3], bd);  \
            }                                                                 \
            _Pragma("unroll")                                                 \
            for (int fm = 0; fm < 4; ++fm)                                    \
                _Pragma("unroll")                                             \
                for (int fn = 0; fn < 4; ++fn)                                \
                    mma16816(acc[fm][fn], afr[fm],                            \
                             bfr[fn >> 1][fn & 1], bfr[fn >> 1][2 + (fn & 1)]); \
        }                                                                     \
    } while (0)

// ===================== generic fp16 GEMM (HMMA) ============================
// C[m][n] = sum_k A[m][k] * B[n][k]; A,B,C fp16 row-major (K-major operands).
// block 128x128, 256 threads, cp.async double-buffered k-chunks of 32.
__global__ __launch_bounds__(256, 1)
void k_gemm16(const __half* __restrict__ A, const __half* __restrict__ B,
              __half* __restrict__ C, long long sA, long long sB, long long sC,
              int lda, int ldb, int ldc, int K) {
    __shared__ __half As[2][128 * SMS];
    __shared__ __half Bs[2][128 * SMS];
    int bm = blockIdx.y * 128, bn = blockIdx.x * 128, b = blockIdx.z;
    A += (long long)b * sA; B += (long long)b * sB; C += (long long)b * sC;
    int t = threadIdx.x, lane = t & 31, wid = t >> 5;
    int wm = (wid & 1) * 64, wn = (wid >> 1) * 32;
    float acc[4][4][4];
#pragma unroll
    for (int i = 0; i < 4; ++i)
#pragma unroll
        for (int j = 0; j < 4; ++j)
#pragma unroll
            for (int q = 0; q < 4; ++q) acc[i][j][q] = 0.f;

    int nk = K / 32;
#pragma unroll 1
    for (int ki = -1; ki < nk; ++ki) {
        int kl = ki + 1;
        if (kl < nk) {
#pragma unroll
            for (int i = 0; i < 2; ++i) {
                int e = t + i * 256, r = e >> 2, s = e & 3;
                CP16(s2u(&As[kl & 1][r * SMS + s * 8]),
                     A + (size_t)(bm + r) * lda + kl * 32 + s * 8);
                CP16(s2u(&Bs[kl & 1][r * SMS + s * 8]),
                     B + (size_t)(bn + r) * ldb + kl * 32 + s * 8);
            }
            CP_COMMIT();
        }
        if (ki < 0) continue;
        if (kl < nk) CP_WAIT1(); else CP_WAIT0();
        __syncthreads();
        const __half* as = As[ki & 1];
        const __half* bs = Bs[ki & 1];
        MMA_CHUNK(as, bs);
        __syncthreads();
    }
#pragma unroll
    for (int fm = 0; fm < 4; ++fm) {
        int r0 = bm + wm + fm * 16 + (lane >> 2);
#pragma unroll
        for (int fn = 0; fn < 4; ++fn) {
            int c = bn + wn + fn * 8 + (lane & 3) * 2;
            *(__half2*)&C[(size_t)r0 * ldc + c] =
                __floats2half2_rn(acc[fm][fn][0], acc[fm][fn][1]);
            *(__half2*)&C[(size_t)(r0 + 8) * ldc + c] =
                __floats2half2_rn(acc[fm][fn][2], acc[fm][fn][3]);
        }
    }
}

// ===================== attn_g GEMM with on-the-fly P =======================
// out[n][c] = sum_m P[n][m] * g[c][m];  P = exp(S - cmax[m]) * cinv[m].
// grid (32 n-tiles, 1, BSZ), 256 threads, K = 4096 (128 chunks).
__global__ __launch_bounds__(256, 1)
void k_attng16() {
    __shared__ __half As[128 * SMS];
    __shared__ __half Bs[2][128 * SMS];
    int b = blockIdx.z, bm = blockIdx.x * 128;
    int t = threadIdx.x, lane = t & 31, wid = t >> 5;
    int wm = (wid & 1) * 64, wn = (wid >> 1) * 32;
    const __half* Sb = g_S16 + (size_t)b * NPIX * NPIX;
    const __half* Bg = g_gh + (size_t)b * HIDD * NPIX;    // rows c, ld NPIX
    const float* cm = g_cmax + b * NPIX;
    const float* ci = g_cinv + b * NPIX;
    __half* Cc = g_agt + (size_t)b * NPIX * HIDD;

    float acc[4][4][4];
#pragma unroll
    for (int i = 0; i < 4; ++i)
#pragma unroll
        for (int j = 0; j < 4; ++j)
#pragma unroll
            for (int q = 0; q < 4; ++q) acc[i][j][q] = 0.f;

    // per-thread S segments: e = t, t+256 -> row r = e>>2, seg s = e&3
    uint4 sv[2];
#pragma unroll
    for (int i = 0; i < 2; ++i) {
        int e = t + i * 256, r = e >> 2, s = e & 3;
        sv[i] = *(const uint4*)&Sb[(size_t)(bm + r) * NPIX + s * 8];
    }
    // B chunk 0
#pragma unroll
    for (int i = 0; i < 2; ++i) {
        int e = t + i * 256, r = e >> 2, s = e & 3;
        CP16(s2u(&Bs[0][r * SMS + s * 8]), Bg + (size_t)r * NPIX + s * 8);
    }
    CP_COMMIT();

#pragma unroll 1
    for (int ki = 0; ki < 128; ++ki) {
        int m0 = ki * 32;
        if (ki < 127) {
#pragma unroll
            for (int i = 0; i < 2; ++i) {
                int e = t + i * 256, r = e >> 2, s = e & 3;
                CP16(s2u(&Bs[(ki + 1) & 1][r * SMS + s * 8]),
                     Bg + (size_t)r * NPIX + (ki + 1) * 32 + s * 8);
            }
            CP_COMMIT();
        }
        // convert current S regs -> P fp16 -> smem A
#pragma unroll
        for (int i = 0; i < 2; ++i) {
            int e = t + i * 256, r = e >> 2, s = e & 3;
            float c8[8], i8[8];
            *(float4*)c8       = *(const float4*)&cm[m0 + s * 8];
            *(float4*)(c8 + 4) = *(const float4*)&cm[m0 + s * 8 + 4];
            *(float4*)i8       = *(const float4*)&ci[m0 + s * 8];
            *(float4*)(i8 + 4) = *(const float4*)&ci[m0 + s * 8 + 4];
            union { uint4 v; __half2 h[4]; } u, o;
            u.v = sv[i];
#pragma unroll
            for (int j = 0; j < 4; ++j) {
                float2 f = __half22float2(u.h[j]);
                float p0 = __expf(f.x - c8[2 * j])     * i8[2 * j];
                float p1 = __expf(f.y - c8[2 * j + 1]) * i8[2 * j + 1];
                o.h[j] = __floats2half2_rn(p0, p1);
            }
            *(uint4*)&As[r * SMS + s * 8] = o.v;
        }
        // prefetch next S chunk
        if (ki < 127) {
#pragma unroll
            for (int i = 0; i < 2; ++i) {
                int e = t + i * 256, r = e >> 2, s = e & 3;
                sv[i] = *(const uint4*)&Sb[(size_t)(bm + r) * NPIX +
                                           (ki + 1) * 32 + s * 8];
            }
        }
        if (ki < 127) CP_WAIT1(); else CP_WAIT0();
        __syncthreads();
        const __half* as = As;
        const __half* bs = Bs[ki & 1];
        MMA_CHUNK(as, bs);
        __syncthreads();
    }
#pragma unroll
    for (int fm = 0; fm < 4; ++fm) {
        int r0 = bm + wm + fm * 16 + (lane >> 2);
#pragma unroll
        for (int fn = 0; fn < 4; ++fn) {
            int c = wn + fn * 8 + (lane & 3) * 2;
            *(__half2*)&Cc[(size_t)r0 * HIDD + c] =
                __floats2half2_rn(acc[fm][fn][0], acc[fm][fn][1]);
            *(__half2*)&Cc[(size_t)(r0 + 8) * HIDD + c] =
                __floats2half2_rn(acc[fm][fn][2], acc[fm][fn][3]);
        }
    }
}

// ===================== mask GEMM + residual (fp32 out) =====================
// out[co][n] = x[co][n] + sum_h whm[co][h] * agt[n][h]. grid (32, 2, BSZ)
__global__ __launch_bounds__(256, 1)
void k_mask16(const float* __restrict__ x, float* __restrict__ out) {
    __shared__ __half As[2][128 * SMS];
    __shared__ __half Bs[2][128 * SMS];
    int bm = blockIdx.y * 128, bn = blockIdx.x * 128, b = blockIdx.z;
    const __half* A = g_whm;                                   // [256][128]
    const __half* B = g_agt + (size_t)b * NPIX * HIDD;         // [4096][128]
    int t = threadIdx.x, lane = t & 31, wid = t >> 5;
    int wm = (wid & 1) * 64, wn = (wid >> 1) * 32;
    float acc[4][4][4];
#pragma unroll
    for (int i = 0; i < 4; ++i)
#pragma unroll
        for (int j = 0; j < 4; ++j)
#pragma unroll
            for (int q = 0; q < 4; ++q) acc[i][j][q] = 0.f;

    const int nk = HIDD / 32;   // 4
#pragma unroll 1
    for (int ki = -1; ki < nk; ++ki) {
        int kl = ki + 1;
        if (kl < nk) {
#pragma unroll
            for (int i = 0; i < 2; ++i) {
                int e = t + i * 256, r = e >> 2, s = e & 3;
                CP16(s2u(&As[kl & 1][r * SMS + s * 8]),
                     A + (size_t)(bm + r) * HIDD + kl * 32 + s * 8);
                CP16(s2u(&Bs[kl & 1][r * SMS + s * 8]),
                     B + (size_t)(bn + r) * HIDD + kl * 32 + s * 8);
            }
            CP_COMMIT();
        }
        if (ki < 0) continue;
        if (kl < nk) CP_WAIT1(); else CP_WAIT0();
        __syncthreads();
        const __half* as = As[ki & 1];
        const __half* bs = Bs[ki & 1];
        MMA_CHUNK(as, bs);
        __syncthreads();
    }
#pragma unroll
    for (int fm = 0; fm < 4; ++fm) {
        int r0 = bm + wm + fm * 16 + (lane >> 2);
#pragma unroll
        for (int fn = 0; fn < 4; ++fn) {
            int c = bn + wn + fn * 8 + (lane & 3) * 2;
            size_t o0 = (size_t)b * CCH * NPIX + (size_t)r0 * NPIX + c;
            size_t o1 = o0 + 8ull * NPIX;
            float2 x0 = *(const float2*)&x[o0];
            float2 x1 = *(const float2*)&x[o1];
            *(float2*)&out[o0] = make_float2(acc[fm][fn][0] + x0.x,
                                             acc[fm][fn][1] + x0.y);
            *(float2*)&out[o1] = make_float2(acc[fm][fn][2] + x1.x,
                                             acc[fm][fn][3] + x1.y);
        }
    }
}

// ===================== small prep / softmax kernels ========================
__global__ void k_wconv(const float* __restrict__ src, __half* __restrict__ dst,
                        int n) {
    int i = blockIdx.x * 256 + threadIdx.x;
    if (i < n) dst[i] = __float2half(src[i]);
}

__global__ void k_xtrans(const float* __restrict__ x) {
    __shared__ float tile[32][33];
    int b = blockIdx.z;
    int n0 = blockIdx.x * 32, c0 = blockIdx.y * 32;
    const float* xb = x + (size_t)b * CCH * NPIX;
    __half* ob = g_xt + (size_t)b * NPIX * CCH;
    int tx = threadIdx.x, ty = threadIdx.y;
#pragma unroll
    for (int i = 0; i < 32; i += 8)
        tile[ty + i][tx] = xb[(size_t)(c0 + ty + i) * NPIX + n0 + tx];
    __syncthreads();
#pragma unroll
    for (int i = 0; i < 32; i += 8)
        ob[(size_t)(n0 + ty + i) * CCH + c0 + tx] = __float2half(tile[tx][ty + i]);
}

// column (axis-n) softmax partial stats over fp16 S. grid (16,16,BSZ), 128 thr
__global__ void k_colstats16() {
    int b = blockIdx.z;
    int m0 = blockIdx.x * 256 + threadIdx.x * 2;
    int nc = blockIdx.y;
    const __half2* Sb = (const __half2*)(g_S16 + (size_t)b * NPIX * NPIX);
    float mx0 = -3.4e38f, mx1 = -3.4e38f, sm0 = 0.f, sm1 = 0.f;
    int nbeg = nc * (NPIX / 16);
#pragma unroll 4
    for (int n = nbeg; n < nbeg + NPIX / 16; ++n) {
        float2 v = __half22float2(Sb[(size_t)n * (NPIX / 2) + (m0 >> 1)]);
        if (v.x > mx0) { sm0 = sm0 * __expf(mx0 - v.x) + 1.f; mx0 = v.x; }
        else           { sm0 += __expf(v.x - mx0); }
        if (v.y > mx1) { sm1 = sm1 * __expf(mx1 - v.y) + 1.f; mx1 = v.y; }
        else           { sm1 += __expf(v.y - mx1); }
    }
    int base = (b * 16 + nc) * NPIX + m0;
    g_pmax[base] = mx0;     g_psum[base] = sm0;
    g_pmax[base + 1] = mx1; g_psum[base + 1] = sm1;
}

__global__ void k_combine() {
    int idx = blockIdx.x * 256 + threadIdx.x;
    int b = idx >> 12, m = idx & 4095;
    float M = -3.4e38f;
#pragma unroll
    for (int c = 0; c < 16; ++c)
        M = fmaxf(M, g_pmax[(b * 16 + c) * NPIX + m]);
    float s = 0.f;
#pragma unroll
    for (int c = 0; c < 16; ++c)
        s += g_psum[(b * 16 + c) * NPIX + m] *
             __expf(g_pmax[(b * 16 + c) * NPIX + m] - M);
    g_cmax[idx] = M;
    g_cinv[idx] = 1.f / s;
}

// ===================== launcher ============================================
extern "C" void kernel_launch(void* const* d_in, const int* in_sizes, int n_in,
                              void* d_out, int out_size) {
    const float* x       = (const float*)d_in[0];
    const float* w_phi   = (const float*)d_in[1];
    const float* w_theta = (const float*)d_in[2];
    const float* w_g     = (const float*)d_in[3];
    const float* w_mask  = (const float*)d_in[4];
    float* out = (float*)d_out;
    (void)in_sizes; (void)n_in; (void)out_size;

    __half *whp, *wht, *whg, *whm, *xt, *tht, *phi, *gh, *S16;
    cudaGetSymbolAddress((void**)&whp, g_whp);
    cudaGetSymbolAddress((void**)&wht, g_wht);
    cudaGetSymbolAddress((void**)&whg, g_whg);
    cudaGetSymbolAddress((void**)&whm, g_whm);
    cudaGetSymbolAddress((void**)&xt,  g_xt);
    cudaGetSymbolAddress((void**)&tht, g_tht);
    cudaGetSymbolAddress((void**)&phi, g_phi);
    cudaGetSymbolAddress((void**)&gh,  g_gh);
    cudaGetSymbolAddress((void**)&S16, g_S16);

    const int NW = HIDD * CCH;   // 32768
    k_wconv<<<(NW + 255) / 256, 256>>>(w_phi,   whp, NW);
    k_wconv<<<(NW + 255) / 256, 256>>>(w_theta, wht, NW);
    k_wconv<<<(NW + 255) / 256, 256>>>(w_g,     whg, NW);
    k_wconv<<<(NW + 255) / 256, 256>>>(w_mask,  whm, NW);
    k_xtrans<<<dim3(NPIX / 32, CCH / 32, BSZ), dim3(32, 8)>>>(x);

    const long long sX = (long long)NPIX * CCH;     // x^T per-batch
    const long long sH = (long long)NPIX * HIDD;    // hid tensors per-batch
    const long long sS = (long long)NPIX * NPIX;    // scores per-batch

    // phi^T[n][o], theta^T[n][o]: A=x^T, B=W. grid (1 n-tile, 32 m-tiles, B)
    k_gemm16<<<dim3(1, 32, BSZ), 256>>>(xt, whp, phi, sX, 0, sH,
                                        CCH, CCH, HIDD, CCH);
    k_gemm16<<<dim3(1, 32, BSZ), 256>>>(xt, wht, tht, sX, 0, sH,
                                        CCH, CCH, HIDD, CCH);
    // g[c][m]: A=W_g, B=x^T. grid (32, 1, B)
    k_gemm16<<<dim3(32, 1, BSZ), 256>>>(whg, xt, gh, 0, sX, sH,
                                        CCH, CCH, NPIX, CCH);
    // S[n][m] = theta^T @ phi^T^T. grid (32, 32, B)
    k_gemm16<<<dim3(32, 32, BSZ), 256>>>(tht, phi, S16, sH, sH, sS,
                                         HIDD, HIDD, NPIX, HIDD);

    k_colstats16<<<dim3(NPIX / 256, 16, BSZ), 128>>>();
    k_combine<<<dim3(BSZ * NPIX / 256), 256>>>();

    k_attng16<<<dim3(NPIX / 128, 1, BSZ), 256>>>();
    k_mask16<<<dim3(NPIX / 128, CCH / 128, BSZ), 256>>>(x, out);
}

// round 4
// speedup vs baseline: 7.3300x; 1.1768x over previous
#include <cuda_runtime.h>
#include <cuda_fp16.h>
#include <math.h>
#include <stdint.h>

#define BSZ   4
#define CCH   256
#define HIDD  128
#define NPIX  4096
#define L2E   1.4426950408889634f

// ---------------- scratch (static device globals) --------------------------
__device__ __half g_xt [(size_t)BSZ * NPIX * CCH];    // x^T  [b][n][c] fp16
__device__ __half g_tht[(size_t)BSZ * NPIX * HIDD];   // theta^T [b][n][c]
__device__ __half g_phi[(size_t)BSZ * NPIX * HIDD];   // phi^T   [b][m][c]
__device__ __half g_gh [(size_t)BSZ * HIDD * NPIX];   // g       [b][c][m]
__device__ __half g_agt[(size_t)BSZ * NPIX * HIDD];   // attn_g^T [b][n][c]
__device__ __half g_S16[(size_t)BSZ * NPIX * NPIX];   // scores fp16 (128 MB)
__device__ __half g_whp[HIDD * CCH];
__device__ __half g_wht[HIDD * CCH];
__device__ __half g_whg[HIDD * CCH];
__device__ __half g_whm[CCH * HIDD];
__device__ float  g_pmax[BSZ * 32 * NPIX];
__device__ float  g_psum[BSZ * 32 * NPIX];
__device__ __half g_nA[BSZ * NPIX];   // -cmax * log2e
__device__ __half g_ci[BSZ * NPIX];   // 1 / colsum

// ---------------- PTX helpers ----------------------------------------------
__device__ __forceinline__ uint32_t s2u(const void* p) {
    return (uint32_t)__cvta_generic_to_shared(p);
}
#define CP16(dst, src) \
    asm volatile("cp.async.cg.shared.global [%0], [%1], 16;" :: "r"(dst), "l"(src))
#define CP_COMMIT() asm volatile("cp.async.commit_group;" ::: "memory")
#define CP_WAIT1()  asm volatile("cp.async.wait_group 1;" ::: "memory")
#define CP_WAIT0()  asm volatile("cp.async.wait_group 0;" ::: "memory")

__device__ __forceinline__ void ldsm_x4(uint32_t& r0, uint32_t& r1,
                                        uint32_t& r2, uint32_t& r3, uint32_t a) {
    asm volatile("ldmatrix.sync.aligned.m8n8.x4.shared.b16 {%0,%1,%2,%3}, [%4];"
                 : "=r"(r0), "=r"(r1), "=r"(r2), "=r"(r3) : "r"(a));
}
__device__ __forceinline__ void mma16816(float* d, const uint32_t* a,
                                         uint32_t b0, uint32_t b1) {
    asm volatile(
        "mma.sync.aligned.m16n8k16.row.col.f32.f16.f16.f32 "
        "{%0,%1,%2,%3}, {%4,%5,%6,%7}, {%8,%9}, {%0,%1,%2,%3};"
        : "+f"(d[0]), "+f"(d[1]), "+f"(d[2]), "+f"(d[3])
        : "r"(a[0]), "r"(a[1]), "r"(a[2]), "r"(a[3]), "r"(b0), "r"(b1));
}
__device__ __forceinline__ uint32_t h2ex2(uint32_t x) {
    uint32_t r;
    asm("ex2.approx.f16x2 %0, %1;" : "=r"(r) : "r"(x));
    return r;
}

#define SMS 40   // generic 32-chunk smem stride (halves)

#define MMA_CHUNK(as, bs)                                                     \
    do {                                                                      \
        _Pragma("unroll")                                                     \
        for (int kk = 0; kk < 2; ++kk) {                                      \
            uint32_t afr[4][4], bfr[2][4];                                    \
            _Pragma("unroll")                                                 \
            for (int fm = 0; fm < 4; ++fm) {                                  \
                uint32_t ad = s2u(&(as)[(wm + fm * 16 + (lane & 15)) * SMS +  \
                                        kk * 16 + (lane >> 4) * 8]);          \
                ldsm_x4(afr[fm][0], afr[fm][1], afr[fm][2], afr[fm][3], ad);  \
            }                                                                 \
            _Pragma("unroll")                                                 \
            for (int fp = 0; fp < 2; ++fp) {                                  \
                uint32_t bd = s2u(&(bs)[(wn + fp * 16 + (lane & 15)) * SMS +  \
                                        kk * 16 + (lane >> 4) * 8]);          \
                ldsm_x4(bfr[fp][0], bfr[fp][1], bfr[fp][2], bfr[fp][3], bd);  \
            }                                                                 \
            _Pragma("unroll")                                                 \
            for (int fm = 0; fm < 4; ++fm)                                    \
                _Pragma("unroll")                                             \
                for (int fn = 0; fn < 4; ++fn)                                \
                    mma16816(acc[fm][fn], afr[fm],                            \
                             bfr[fn >> 1][fn & 1], bfr[fn >> 1][2 + (fn & 1)]); \
        }                                                                     \
    } while (0)

#define ACC_ZERO()                                                            \
    float acc[4][4][4];                                                       \
    _Pragma("unroll")                                                         \
    for (int i = 0; i < 4; ++i)                                               \
        _Pragma("unroll")                                                     \
        for (int j = 0; j < 4; ++j)                                           \
            _Pragma("unroll")                                                 \
            for (int q = 0; q < 4; ++q) acc[i][j][q] = 0.f

// ===================== generic fp16 GEMM (32-chunk, double-buffered) =======
__global__ __launch_bounds__(256, 1)
void k_gemm16(const __half* __restrict__ A, const __half* __restrict__ B,
              __half* __restrict__ C, long long sA, long long sB, long long sC,
              int lda, int ldb, int ldc, int K) {
    __shared__ __half As[2][128 * SMS];
    __shared__ __half Bs[2][128 * SMS];
    int bm = blockIdx.y * 128, bn = blockIdx.x * 128, b = blockIdx.z;
    A += (long long)b * sA; B += (long long)b * sB; C += (long long)b * sC;
    int t = threadIdx.x, lane = t & 31, wid = t >> 5;
    int wm = (wid & 1) * 64, wn = (wid >> 1) * 32;
    ACC_ZERO();
    int nk = K / 32;
#pragma unroll 1
    for (int ki = -1; ki < nk; ++ki) {
        int kl = ki + 1;
        if (kl < nk) {
#pragma unroll
            for (int i = 0; i < 2; ++i) {
                int e = t + i * 256, r = e >> 2, s = e & 3;
                CP16(s2u(&As[kl & 1][r * SMS + s * 8]),
                     A + (size_t)(bm + r) * lda + kl * 32 + s * 8);
                CP16(s2u(&Bs[kl & 1][r * SMS + s * 8]),
                     B + (size_t)(bn + r) * ldb + kl * 32 + s * 8);
            }
            CP_COMMIT();
        }
        if (ki < 0) continue;
        if (kl < nk) CP_WAIT1(); else CP_WAIT0();
        __syncthreads();
        const __half* as = As[ki & 1];
        const __half* bs = Bs[ki & 1];
        MMA_CHUNK(as, bs);
        __syncthreads();
    }
#pragma unroll
    for (int fm = 0; fm < 4; ++fm) {
        int r0 = bm + wm + fm * 16 + (lane >> 2);
#pragma unroll
        for (int fn = 0; fn < 4; ++fn) {
            int c = bn + wn + fn * 8 + (lane & 3) * 2;
            *(__half2*)&C[(size_t)r0 * ldc + c] =
                __floats2half2_rn(acc[fm][fn][0], acc[fm][fn][1]);
            *(__half2*)&C[(size_t)(r0 + 8) * ldc + c] =
                __floats2half2_rn(acc[fm][fn][2], acc[fm][fn][3]);
        }
    }
}

// ===================== phi + theta merged projection =======================
// grid (2, 32, BSZ): x selects (W, C); C[n][o] = sum_c x^T[n][c] W[o][c]
__global__ __launch_bounds__(256, 1)
void k_qkvPT() {
    __shared__ __half As[2][128 * SMS];
    __shared__ __half Bs[2][128 * SMS];
    int which = blockIdx.x, bm = blockIdx.y * 128, b = blockIdx.z;
    const __half* A = g_xt + (size_t)b * NPIX * CCH;
    const __half* B = which ? g_wht : g_whp;
    __half* C = (which ? g_tht : g_phi) + (size_t)b * NPIX * HIDD;
    int t = threadIdx.x, lane = t & 31, wid = t >> 5;
    int wm = (wid & 1) * 64, wn = (wid >> 1) * 32;
    ACC_ZERO();
    const int nk = CCH / 32;
#pragma unroll 1
    for (int ki = -1; ki < nk; ++ki) {
        int kl = ki + 1;
        if (kl < nk) {
#pragma unroll
            for (int i = 0; i < 2; ++i) {
                int e = t + i * 256, r = e >> 2, s = e & 3;
                CP16(s2u(&As[kl & 1][r * SMS + s * 8]),
                     A + (size_t)(bm + r) * CCH + kl * 32 + s * 8);
                CP16(s2u(&Bs[kl & 1][r * SMS + s * 8]),
                     B + (size_t)r * CCH + kl * 32 + s * 8);
            }
            CP_COMMIT();
        }
        if (ki < 0) continue;
        if (kl < nk) CP_WAIT1(); else CP_WAIT0();
        __syncthreads();
        const __half* as = As[ki & 1];
        const __half* bs = Bs[ki & 1];
        MMA_CHUNK(as, bs);
        __syncthreads();
    }
#pragma unroll
    for (int fm = 0; fm < 4; ++fm) {
        int r0 = bm + wm + fm * 16 + (lane >> 2);
#pragma unroll
        for (int fn = 0; fn < 4; ++fn) {
            int c = wn + fn * 8 + (lane & 3) * 2;
            *(__half2*)&C[(size_t)r0 * HIDD + c] =
                __floats2half2_rn(acc[fm][fn][0], acc[fm][fn][1]);
            *(__half2*)&C[(size_t)(r0 + 8) * HIDD + c] =
                __floats2half2_rn(acc[fm][fn][2], acc[fm][fn][3]);
        }
    }
}

// ===================== scores (K=128 resident) + fused softmax stats =======
#define SCS 136
#define SC_SMEM (2 * 128 * SCS * 2)

__global__ __launch_bounds__(256, 1)
void k_scores16() {
    extern __shared__ __half sm[];
    __half* As = sm;
    __half* Bs = sm + 128 * SCS;
    int b = blockIdx.z, n0 = blockIdx.y * 128, m0 = blockIdx.x * 128;
    const __half* At = g_tht + (size_t)b * NPIX * HIDD;
    const __half* Bt = g_phi + (size_t)b * NPIX * HIDD;
    int t = threadIdx.x, lane = t & 31, wid = t >> 5;
    int wm = (wid & 1) * 64, wn = (wid >> 1) * 32;

#pragma unroll
    for (int i = 0; i < 8; ++i) {
        int e = t + i * 256, r = e >> 4, s = e & 15;
        CP16(s2u(&As[r * SCS + s * 8]), At + (size_t)(n0 + r) * HIDD + s * 8);
        CP16(s2u(&Bs[r * SCS + s * 8]), Bt + (size_t)(m0 + r) * HIDD + s * 8);
    }
    CP_COMMIT();
    ACC_ZERO();
    CP_WAIT0();
    __syncthreads();

#pragma unroll
    for (int kk = 0; kk < 8; ++kk) {
        uint32_t afr[4][4], bfr[2][4];
#pragma unroll
        for (int fm = 0; fm < 4; ++fm)
            ldsm_x4(afr[fm][0], afr[fm][1], afr[fm][2], afr[fm][3],
                    s2u(&As[(wm + fm * 16 + (lane & 15)) * SCS +
                            kk * 16 + (lane >> 4) * 8]));
#pragma unroll
        for (int fp = 0; fp < 2; ++fp)
            ldsm_x4(bfr[fp][0], bfr[fp][1], bfr[fp][2], bfr[fp][3],
                    s2u(&Bs[(wn + fp * 16 + (lane & 15)) * SCS +
                            kk * 16 + (lane >> 4) * 8]));
#pragma unroll
        for (int fm = 0; fm < 4; ++fm)
#pragma unroll
            for (int fn = 0; fn < 4; ++fn)
                mma16816(acc[fm][fn], afr[fm],
                         bfr[fn >> 1][fn & 1], bfr[fn >> 1][2 + (fn & 1)]);
    }

    // ---- write S16, keep half pairs for stats ----
    uint32_t hs[4][4][2];
    __half* Srow = g_S16 + (size_t)b * NPIX * NPIX;
#pragma unroll
    for (int fm = 0; fm < 4; ++fm) {
        int r0 = n0 + wm + fm * 16 + (lane >> 2);
#pragma unroll
        for (int fn = 0; fn < 4; ++fn) {
            int c = m0 + wn + fn * 8 + (lane & 3) * 2;
            __half2 h0 = __floats2half2_rn(acc[fm][fn][0], acc[fm][fn][1]);
            __half2 h1 = __floats2half2_rn(acc[fm][fn][2], acc[fm][fn][3]);
            hs[fm][fn][0] = *(uint32_t*)&h0;
            hs[fm][fn][1] = *(uint32_t*)&h1;
            *(__half2*)&Srow[(size_t)r0 * NPIX + c] = h0;
            *(__half2*)&Srow[(size_t)(r0 + 8) * NPIX + c] = h1;
        }
    }

    // ---- tile-local column max (over the 128 n-rows) ----
    float lv[8];
#pragma unroll
    for (int fn = 0; fn < 4; ++fn)
#pragma unroll
        for (int q = 0; q < 2; ++q) {
            float mv = -3.4e38f;
#pragma unroll
            for (int fm = 0; fm < 4; ++fm) {
                mv = fmaxf(mv, acc[fm][fn][q]);
                mv = fmaxf(mv, acc[fm][fn][q + 2]);
            }
            lv[fn * 2 + q] = mv;
        }
#pragma unroll
    for (int d = 4; d < 32; d <<= 1)
#pragma unroll
        for (int j = 0; j < 8; ++j)
            lv[j] = fmaxf(lv[j], __shfl_xor_sync(0xffffffffu, lv[j], d));
    __syncthreads();                       // smem reuse barrier
    float* red = (float*)sm;               // [2][128]
    float* cmx = (float*)sm + 256;         // [128]
    if (lane < 4)
#pragma unroll
        for (int j = 0; j < 8; ++j)
            red[(wid & 1) * 128 + wn + (j >> 1) * 8 + (lane & 3) * 2 + (j & 1)] = lv[j];
    __syncthreads();
    if (t < 128) cmx[t] = fmaxf(red[t], red[128 + t]);
    __syncthreads();

    // ---- tile-local column sum of exp (half2 ex2 on stored pairs) ----
    float sums[8] = {0.f, 0.f, 0.f, 0.f, 0.f, 0.f, 0.f, 0.f};
    __half2 l2 = __float2half2_rn(L2E);
#pragma unroll
    for (int fn = 0; fn < 4; ++fn) {
        int c0 = wn + fn * 8 + (lane & 3) * 2;
        __half2 nc2 = __floats2half2_rn(-cmx[c0] * L2E, -cmx[c0 + 1] * L2E);
#pragma unroll
        for (int fm = 0; fm < 4; ++fm)
#pragma unroll
            for (int h = 0; h < 2; ++h) {
                __half2 v = *(__half2*)&hs[fm][fn][h];
                __half2 a2 = __hfma2(v, l2, nc2);
                uint32_t p = h2ex2(*(uint32_t*)&a2);
                float2 f = __half22float2(*(__half2*)&p);
                sums[fn * 2]     += f.x;
                sums[fn * 2 + 1] += f.y;
            }
    }
#pragma unroll
    for (int d = 4; d < 32; d <<= 1)
#pragma unroll
        for (int j = 0; j < 8; ++j)
            sums[j] += __shfl_xor_sync(0xffffffffu, sums[j], d);
    __syncthreads();
    if (lane < 4)
#pragma unroll
        for (int j = 0; j < 8; ++j)
            red[(wid & 1) * 128 + wn + (j >> 1) * 8 + (lane & 3) * 2 + (j & 1)] = sums[j];
    __syncthreads();
    if (t < 128) {
        int base = (b * 32 + blockIdx.y) * NPIX + m0 + t;
        g_pmax[base] = cmx[t];
        g_psum[base] = red[t] + red[128 + t];
    }
}

// combine 32 partials -> -cmax*log2e (half), 1/colsum (half). grid 64 x 256
__global__ void k_combine32() {
    int idx = blockIdx.x * 256 + threadIdx.x;
    int b = idx >> 12, m = idx & 4095;
    float M = -3.4e38f;
#pragma unroll
    for (int c = 0; c < 32; ++c)
        M = fmaxf(M, g_pmax[(b * 32 + c) * NPIX + m]);
    float s = 0.f;
#pragma unroll
    for (int c = 0; c < 32; ++c)
        s += g_psum[(b * 32 + c) * NPIX + m] *
             __expf(g_pmax[(b * 32 + c) * NPIX + m] - M);
    g_nA[idx] = __float2half(-M * L2E);
    g_ci[idx] = __float2half(1.f / s);
}

// ===================== attn_g: on-the-fly fp16 P, chunk=64 =================
#define AGS 72
#define AG_SMEM (3 * 128 * AGS * 2)

__global__ __launch_bounds__(256, 1)
void k_attng16() {
    extern __shared__ __half sm[];
    __half* As = sm;                         // 128 x 72
    __half* BsA[2] = {sm + 128 * AGS, sm + 2 * 128 * AGS};
    int b = blockIdx.z, bm = blockIdx.x * 128;
    int t = threadIdx.x, lane = t & 31, wid = t >> 5;
    int wm = (wid & 1) * 64, wn = (wid >> 1) * 32;
    int r4 = t >> 3, s8 = t & 7;
    const __half* Sb = g_S16 + (size_t)b * NPIX * NPIX;
    const __half* Bg = g_gh + (size_t)b * HIDD * NPIX;
    const __half* nA = g_nA + b * NPIX;
    const __half* ci = g_ci + b * NPIX;
    __half* Cc = g_agt + (size_t)b * NPIX * HIDD;
    ACC_ZERO();

    uint4 sv[4];
#pragma unroll
    for (int i = 0; i < 4; ++i)
        sv[i] = *(const uint4*)&Sb[(size_t)(bm + r4 + i * 32) * NPIX + s8 * 8];
#pragma unroll
    for (int i = 0; i < 4; ++i)
        CP16(s2u(&BsA[0][(r4 + i * 32) * AGS + s8 * 8]),
             Bg + (size_t)(r4 + i * 32) * NPIX + s8 * 8);
    CP_COMMIT();

    const __half2 l2 = __float2half2_rn(L2E);
#pragma unroll 1
    for (int ki = 0; ki < 64; ++ki) {
        int m0 = ki * 64;
        if (ki < 63) {
#pragma unroll
            for (int i = 0; i < 4; ++i)
                CP16(s2u(&BsA[(ki + 1) & 1][(r4 + i * 32) * AGS + s8 * 8]),
                     Bg + (size_t)(r4 + i * 32) * NPIX + m0 + 64 + s8 * 8);
            CP_COMMIT();
        }
        union { uint4 v; __half2 h[4]; } ua, uc;
        ua.v = *(const uint4*)&nA[m0 + s8 * 8];
        uc.v = *(const uint4*)&ci[m0 + s8 * 8];
#pragma unroll
        for (int i = 0; i < 4; ++i) {
            union { uint4 v; __half2 h[4]; } u, o;
            u.v = sv[i];
#pragma unroll
            for (int j = 0; j < 4; ++j) {
                __half2 a2 = __hfma2(u.h[j], l2, ua.h[j]);
                uint32_t p = h2ex2(*(uint32_t*)&a2);
                o.h[j] = __hmul2(*(__half2*)&p, uc.h[j]);
            }
            *(uint4*)&As[(r4 + i * 32) * AGS + s8 * 8] = o.v;
        }
        if (ki < 63) {
#pragma unroll
            for (int i = 0; i < 4; ++i)
                sv[i] = *(const uint4*)&Sb[(size_t)(bm + r4 + i * 32) * NPIX +
                                           m0 + 64 + s8 * 8];
        }
        if (ki < 63) CP_WAIT1(); else CP_WAIT0();
        __syncthreads();
        const __half* bs = BsA[ki & 1];
#pragma unroll
        for (int kk = 0; kk < 4; ++kk) {
            uint32_t afr[4][4], bfr[2][4];
#pragma unroll
            for (int fm = 0; fm < 4; ++fm)
                ldsm_x4(afr[fm][0], afr[fm][1], afr[fm][2], afr[fm][3],
                        s2u(&As[(wm + fm * 16 + (lane & 15)) * AGS +
                                kk * 16 + (lane >> 4) * 8]));
#pragma unroll
            for (int fp = 0; fp < 2; ++fp)
                ldsm_x4(bfr[fp][0], bfr[fp][1], bfr[fp][2], bfr[fp][3],
                        s2u(&bs[(wn + fp * 16 + (lane & 15)) * AGS +
                                kk * 16 + (lane >> 4) * 8]));
#pragma unroll
            for (int fm = 0; fm < 4; ++fm)
#pragma unroll
                for (int fn = 0; fn < 4; ++fn)
                    mma16816(acc[fm][fn], afr[fm],
                             bfr[fn >> 1][fn & 1], bfr[fn >> 1][2 + (fn & 1)]);
        }
        __syncthreads();
    }
#pragma unroll
    for (int fm = 0; fm < 4; ++fm) {
        int r0 = bm + wm + fm * 16 + (lane >> 2);
#pragma unroll
        for (int fn = 0; fn < 4; ++fn) {
            int c = wn + fn * 8 + (lane & 3) * 2;
            *(__half2*)&Cc[(size_t)r0 * HIDD + c] =
                __floats2half2_rn(acc[fm][fn][0], acc[fm][fn][1]);
            *(__half2*)&Cc[(size_t)(r0 + 8) * HIDD + c] =
                __floats2half2_rn(acc[fm][fn][2], acc[fm][fn][3]);
        }
    }
}

// ===================== mask GEMM + residual (fp32 out) =====================
__global__ __launch_bounds__(256, 1)
void k_mask16(const float* __restrict__ x, float* __restrict__ out) {
    __shared__ __half As[2][128 * SMS];
    __shared__ __half Bs[2][128 * SMS];
    int bm = blockIdx.y * 128, bn = blockIdx.x * 128, b = blockIdx.z;
    const __half* A = g_whm;
    const __half* B = g_agt + (size_t)b * NPIX * HIDD;
    int t = threadIdx.x, lane = t & 31, wid = t >> 5;
    int wm = (wid & 1) * 64, wn = (wid >> 1) * 32;
    ACC_ZERO();
    const int nk = HIDD / 32;
#pragma unroll 1
    for (int ki = -1; ki < nk; ++ki) {
        int kl = ki + 1;
        if (kl < nk) {
#pragma unroll
            for (int i = 0; i < 2; ++i) {
                int e = t + i * 256, r = e >> 2, s = e & 3;
                CP16(s2u(&As[kl & 1][r * SMS + s * 8]),
                     A + (size_t)(bm + r) * HIDD + kl * 32 + s * 8);
                CP16(s2u(&Bs[kl & 1][r * SMS + s * 8]),
                     B + (size_t)(bn + r) * HIDD + kl * 32 + s * 8);
            }
            CP_COMMIT();
        }
        if (ki < 0) continue;
        if (kl < nk) CP_WAIT1(); else CP_WAIT0();
        __syncthreads();
        const __half* as = As[ki & 1];
        const __half* bs = Bs[ki & 1];
        MMA_CHUNK(as, bs);
        __syncthreads();
    }
#pragma unroll
    for (int fm = 0; fm < 4; ++fm) {
        int r0 = bm + wm + fm * 16 + (lane >> 2);
#pragma unroll
        for (int fn = 0; fn < 4; ++fn) {
            int c = bn + wn + fn * 8 + (lane & 3) * 2;
            size_t o0 = (size_t)b * CCH * NPIX + (size_t)r0 * NPIX + c;
            size_t o1 = o0 + 8ull * NPIX;
            float2 x0 = *(const float2*)&x[o0];
            float2 x1 = *(const float2*)&x[o1];
            *(float2*)&out[o0] = make_float2(acc[fm][fn][0] + x0.x,
                                             acc[fm][fn][1] + x0.y);
            *(float2*)&out[o1] = make_float2(acc[fm][fn][2] + x1.x,
                                             acc[fm][fn][3] + x1.y);
        }
    }
}

// ===================== prep kernels ========================================
__global__ void k_wconv4(const float* __restrict__ a, const float* __restrict__ b,
                         const float* __restrict__ c, const float* __restrict__ d) {
    int i = blockIdx.x * 256 + threadIdx.x;   // 0 .. 131071
    int w = i >> 15, j = i & 32767;
    const float* src = w == 0 ? a : (w == 1 ? b : (w == 2 ? c : d));
    __half* dst = w == 0 ? g_whp : (w == 1 ? g_wht : (w == 2 ? g_whg : g_whm));
    dst[j] = __float2half(src[j]);
}

__global__ void k_xtrans(const float* __restrict__ x) {
    __shared__ float tile[32][33];
    int b = blockIdx.z;
    int n0 = blockIdx.x * 32, c0 = blockIdx.y * 32;
    const float* xb = x + (size_t)b * CCH * NPIX;
    __half* ob = g_xt + (size_t)b * NPIX * CCH;
    int tx = threadIdx.x, ty = threadIdx.y;
#pragma unroll
    for (int i = 0; i < 32; i += 8)
        tile[ty + i][tx] = xb[(size_t)(c0 + ty + i) * NPIX + n0 + tx];
    __syncthreads();
#pragma unroll
    for (int i = 0; i < 32; i += 8)
        ob[(size_t)(n0 + ty + i) * CCH + c0 + tx] = __float2half(tile[tx][ty + i]);
}

// ===================== launcher ============================================
extern "C" void kernel_launch(void* const* d_in, const int* in_sizes, int n_in,
                              void* d_out, int out_size) {
    const float* x       = (const float*)d_in[0];
    const float* w_phi   = (const float*)d_in[1];
    const float* w_theta = (const float*)d_in[2];
    const float* w_g     = (const float*)d_in[3];
    const float* w_mask  = (const float*)d_in[4];
    float* out = (float*)d_out;
    (void)in_sizes; (void)n_in; (void)out_size;

    static int attr_done = 0;
    if (!attr_done) {
        cudaFuncSetAttribute(k_scores16, cudaFuncAttributeMaxDynamicSharedMemorySize,
                             SC_SMEM);
        cudaFuncSetAttribute(k_attng16, cudaFuncAttributeMaxDynamicSharedMemorySize,
                             AG_SMEM);
        attr_done = 1;
    }

    __half *whg, *xt, *gh;
    cudaGetSymbolAddress((void**)&whg, g_whg);
    cudaGetSymbolAddress((void**)&xt,  g_xt);
    cudaGetSymbolAddress((void**)&gh,  g_gh);

    k_wconv4<<<512, 256>>>(w_phi, w_theta, w_g, w_mask);
    k_xtrans<<<dim3(NPIX / 32, CCH / 32, BSZ), dim3(32, 8)>>>(x);

    const long long sX = (long long)NPIX * CCH;
    const long long sH = (long long)NPIX * HIDD;

    k_qkvPT<<<dim3(2, 32, BSZ), 256>>>();
    k_gemm16<<<dim3(32, 1, BSZ), 256>>>(whg, xt, gh, 0, sX, sH,
                                        CCH, CCH, NPIX, CCH);
    k_scores16<<<dim3(32, 32, BSZ), 256, SC_SMEM>>>();
    k_combine32<<<dim3(BSZ * NPIX / 256), 256>>>();
    k_attng16<<<dim3(NPIX / 128, 1, BSZ), 256, AG_SMEM>>>();
    k_mask16<<<dim3(NPIX / 128, CCH / 128, BSZ), 256>>>(x, out);
}

// round 5
// speedup vs baseline: 11.7548x; 1.6036x over previous
#include <cuda_runtime.h>
#include <cuda_fp16.h>
#include <math.h>
#include <stdint.h>

#define BSZ   4
#define CCH   256
#define HIDD  128
#define NPIX  4096
#define L2E   1.4426950408889634f

// ---------------- scratch ---------------------------------------------------
__device__ __half g_xt [(size_t)BSZ * NPIX * CCH];
__device__ __half g_tht[(size_t)BSZ * NPIX * HIDD];
__device__ __half g_phi[(size_t)BSZ * NPIX * HIDD];
__device__ __half g_gh [(size_t)BSZ * HIDD * NPIX];
__device__ __half g_agt[(size_t)BSZ * NPIX * HIDD];
__device__ __half g_S16[(size_t)BSZ * NPIX * NPIX];
__device__ __half g_whp[HIDD * CCH];
__device__ __half g_wht[HIDD * CCH];
__device__ __half g_whg[HIDD * CCH];
__device__ __half g_whm[CCH * HIDD];
__device__ float  g_pmax[BSZ * 32 * NPIX];
__device__ float  g_psum[BSZ * 32 * NPIX];
__device__ __half g_nA[BSZ * NPIX];
__device__ __half g_ci[BSZ * NPIX];

// ---------------- PTX helpers ----------------------------------------------
__device__ __forceinline__ uint32_t s2u(const void* p) {
    return (uint32_t)__cvta_generic_to_shared(p);
}
#define CP16(dst, src) \
    asm volatile("cp.async.cg.shared.global [%0], [%1], 16;" :: "r"(dst), "l"(src))
#define CP_COMMIT() asm volatile("cp.async.commit_group;" ::: "memory")
#define CP_WAIT1()  asm volatile("cp.async.wait_group 1;" ::: "memory")
#define CP_WAIT0()  asm volatile("cp.async.wait_group 0;" ::: "memory")

__device__ __forceinline__ void ldsm_x4(uint32_t& r0, uint32_t& r1,
                                        uint32_t& r2, uint32_t& r3, uint32_t a) {
    asm volatile("ldmatrix.sync.aligned.m8n8.x4.shared.b16 {%0,%1,%2,%3}, [%4];"
                 : "=r"(r0), "=r"(r1), "=r"(r2), "=r"(r3) : "r"(a));
}
__device__ __forceinline__ void mma16816(float* d, const uint32_t* a,
                                         uint32_t b0, uint32_t b1) {
    asm volatile(
        "mma.sync.aligned.m16n8k16.row.col.f32.f16.f16.f32 "
        "{%0,%1,%2,%3}, {%4,%5,%6,%7}, {%8,%9}, {%0,%1,%2,%3};"
        : "+f"(d[0]), "+f"(d[1]), "+f"(d[2]), "+f"(d[3])
        : "r"(a[0]), "r"(a[1]), "r"(a[2]), "r"(a[3]), "r"(b0), "r"(b1));
}
__device__ __forceinline__ uint32_t h2ex2(uint32_t x) {
    uint32_t r;
    asm("ex2.approx.f16x2 %0, %1;" : "=r"(r) : "r"(x));
    return r;
}

#define SMS 40

// 128-row tile chunk (warp tiles 64x32)
#define MMA_CHUNK(as, bs)                                                     \
    do {                                                                      \
        _Pragma("unroll")                                                     \
        for (int kk = 0; kk < 2; ++kk) {                                      \
            uint32_t afr[4][4], bfr[2][4];                                    \
            _Pragma("unroll")                                                 \
            for (int fm = 0; fm < 4; ++fm)                                    \
                ldsm_x4(afr[fm][0], afr[fm][1], afr[fm][2], afr[fm][3],       \
                        s2u(&(as)[(wm + fm * 16 + (lane & 15)) * SMS +        \
                                  kk * 16 + (lane >> 4) * 8]));               \
            _Pragma("unroll")                                                 \
            for (int fp = 0; fp < 2; ++fp)                                    \
                ldsm_x4(bfr[fp][0], bfr[fp][1], bfr[fp][2], bfr[fp][3],       \
                        s2u(&(bs)[(wn + fp * 16 + (lane & 15)) * SMS +        \
                                  kk * 16 + (lane >> 4) * 8]));               \
            _Pragma("unroll")                                                 \
            for (int fm = 0; fm < 4; ++fm)                                    \
                _Pragma("unroll")                                             \
                for (int fn = 0; fn < 4; ++fn)                                \
                    mma16816(acc[fm][fn], afr[fm],                            \
                             bfr[fn >> 1][fn & 1], bfr[fn >> 1][2 + (fn & 1)]); \
        }                                                                     \
    } while (0)

// 64-row tile chunk (warp tiles 32x32)
#define MMA_CHUNK64(as, bs)                                                   \
    do {                                                                      \
        _Pragma("unroll")                                                     \
        for (int kk = 0; kk < 2; ++kk) {                                      \
            uint32_t afr[2][4], bfr[2][4];                                    \
            _Pragma("unroll")                                                 \
            for (int fm = 0; fm < 2; ++fm)                                    \
                ldsm_x4(afr[fm][0], afr[fm][1], afr[fm][2], afr[fm][3],       \
                        s2u(&(as)[(wm + fm * 16 + (lane & 15)) * SMS +        \
                                  kk * 16 + (lane >> 4) * 8]));               \
            _Pragma("unroll")                                                 \
            for (int fp = 0; fp < 2; ++fp)                                    \
                ldsm_x4(bfr[fp][0], bfr[fp][1], bfr[fp][2], bfr[fp][3],       \
                        s2u(&(bs)[(wn + fp * 16 + (lane & 15)) * SMS +        \
                                  kk * 16 + (lane >> 4) * 8]));               \
            _Pragma("unroll")                                                 \
            for (int fm = 0; fm < 2; ++fm)                                    \
                _Pragma("unroll")                                             \
                for (int fn = 0; fn < 4; ++fn)                                \
                    mma16816(acc[fm][fn], afr[fm],                            \
                             bfr[fn >> 1][fn & 1], bfr[fn >> 1][2 + (fn & 1)]); \
        }                                                                     \
    } while (0)

#define ACC_ZERO(NM)                                                          \
    float acc[NM][4][4];                                                      \
    _Pragma("unroll")                                                         \
    for (int i = 0; i < NM; ++i)                                              \
        _Pragma("unroll")                                                     \
        for (int j = 0; j < 4; ++j)                                           \
            _Pragma("unroll")                                                 \
            for (int q = 0; q < 4; ++q) acc[i][j][q] = 0.f

// ===================== generic GEMM, M-tile 64 =============================
__global__ __launch_bounds__(256, 2)
void k_gemm16_64(const __half* __restrict__ A, const __half* __restrict__ B,
                 __half* __restrict__ C, long long sA, long long sB,
                 long long sC, int lda, int ldb, int ldc, int K) {
    __shared__ __half As[2][64 * SMS];
    __shared__ __half Bs[2][128 * SMS];
    int bm = blockIdx.y * 64, bn = blockIdx.x * 128, b = blockIdx.z;
    A += (long long)b * sA; B += (long long)b * sB; C += (long long)b * sC;
    int t = threadIdx.x, lane = t & 31, wid = t >> 5;
    int wm = (wid & 1) * 32, wn = (wid >> 1) * 32;
    ACC_ZERO(2);
    int nk = K / 32;
#pragma unroll 1
    for (int ki = -1; ki < nk; ++ki) {
        int kl = ki + 1;
        if (kl < nk) {
            {   // A: 64 rows x 32 = 256 threads x 1
                int r = t >> 2, s = t & 3;
                CP16(s2u(&As[kl & 1][r * SMS + s * 8]),
                     A + (size_t)(bm + r) * lda + kl * 32 + s * 8);
            }
#pragma unroll
            for (int i = 0; i < 2; ++i) {
                int e = t + i * 256, r = e >> 2, s = e & 3;
                CP16(s2u(&Bs[kl & 1][r * SMS + s * 8]),
                     B + (size_t)(bn + r) * ldb + kl * 32 + s * 8);
            }
            CP_COMMIT();
        }
        if (ki < 0) continue;
        if (kl < nk) CP_WAIT1(); else CP_WAIT0();
        __syncthreads();
        const __half* as = As[ki & 1];
        const __half* bs = Bs[ki & 1];
        MMA_CHUNK64(as, bs);
        __syncthreads();
    }
#pragma unroll
    for (int fm = 0; fm < 2; ++fm) {
        int r0 = bm + wm + fm * 16 + (lane >> 2);
#pragma unroll
        for (int fn = 0; fn < 4; ++fn) {
            int c = bn + wn + fn * 8 + (lane & 3) * 2;
            *(__half2*)&C[(size_t)r0 * ldc + c] =
                __floats2half2_rn(acc[fm][fn][0], acc[fm][fn][1]);
            *(__half2*)&C[(size_t)(r0 + 8) * ldc + c] =
                __floats2half2_rn(acc[fm][fn][2], acc[fm][fn][3]);
        }
    }
}

// ===================== phi + theta merged projection =======================
__global__ __launch_bounds__(256, 2)
void k_qkvPT() {
    __shared__ __half As[2][128 * SMS];
    __shared__ __half Bs[2][128 * SMS];
    int which = blockIdx.x, bm = blockIdx.y * 128, b = blockIdx.z;
    const __half* A = g_xt + (size_t)b * NPIX * CCH;
    const __half* B = which ? g_wht : g_whp;
    __half* C = (which ? g_tht : g_phi) + (size_t)b * NPIX * HIDD;
    int t = threadIdx.x, lane = t & 31, wid = t >> 5;
    int wm = (wid & 1) * 64, wn = (wid >> 1) * 32;
    ACC_ZERO(4);
    const int nk = CCH / 32;
#pragma unroll 1
    for (int ki = -1; ki < nk; ++ki) {
        int kl = ki + 1;
        if (kl < nk) {
#pragma unroll
            for (int i = 0; i < 2; ++i) {
                int e = t + i * 256, r = e >> 2, s = e & 3;
                CP16(s2u(&As[kl & 1][r * SMS + s * 8]),
                     A + (size_t)(bm + r) * CCH + kl * 32 + s * 8);
                CP16(s2u(&Bs[kl & 1][r * SMS + s * 8]),
                     B + (size_t)r * CCH + kl * 32 + s * 8);
            }
            CP_COMMIT();
        }
        if (ki < 0) continue;
        if (kl < nk) CP_WAIT1(); else CP_WAIT0();
        __syncthreads();
        const __half* as = As[ki & 1];
        const __half* bs = Bs[ki & 1];
        MMA_CHUNK(as, bs);
        __syncthreads();
    }
#pragma unroll
    for (int fm = 0; fm < 4; ++fm) {
        int r0 = bm + wm + fm * 16 + (lane >> 2);
#pragma unroll
        for (int fn = 0; fn < 4; ++fn) {
            int c = wn + fn * 8 + (lane & 3) * 2;
            *(__half2*)&C[(size_t)r0 * HIDD + c] =
                __floats2half2_rn(acc[fm][fn][0], acc[fm][fn][1]);
            *(__half2*)&C[(size_t)(r0 + 8) * HIDD + c] =
                __floats2half2_rn(acc[fm][fn][2], acc[fm][fn][3]);
        }
    }
}

// ===================== scores + fused softmax stats ========================
#define SCS 136
#define SC_SMEM (2 * 128 * SCS * 2)

__global__ __launch_bounds__(256, 2)
void k_scores16() {
    extern __shared__ __half sm[];
    __half* As = sm;
    __half* Bs = sm + 128 * SCS;
    int b = blockIdx.z, n0 = blockIdx.y * 128, m0 = blockIdx.x * 128;
    const __half* At = g_tht + (size_t)b * NPIX * HIDD;
    const __half* Bt = g_phi + (size_t)b * NPIX * HIDD;
    int t = threadIdx.x, lane = t & 31, wid = t >> 5;
    int wm = (wid & 1) * 64, wn = (wid >> 1) * 32;

#pragma unroll
    for (int i = 0; i < 8; ++i) {
        int e = t + i * 256, r = e >> 4, s = e & 15;
        CP16(s2u(&As[r * SCS + s * 8]), At + (size_t)(n0 + r) * HIDD + s * 8);
        CP16(s2u(&Bs[r * SCS + s * 8]), Bt + (size_t)(m0 + r) * HIDD + s * 8);
    }
    CP_COMMIT();
    ACC_ZERO(4);
    CP_WAIT0();
    __syncthreads();

#pragma unroll
    for (int kk = 0; kk < 8; ++kk) {
        uint32_t afr[4][4], bfr[2][4];
#pragma unroll
        for (int fm = 0; fm < 4; ++fm)
            ldsm_x4(afr[fm][0], afr[fm][1], afr[fm][2], afr[fm][3],
                    s2u(&As[(wm + fm * 16 + (lane & 15)) * SCS +
                            kk * 16 + (lane >> 4) * 8]));
#pragma unroll
        for (int fp = 0; fp < 2; ++fp)
            ldsm_x4(bfr[fp][0], bfr[fp][1], bfr[fp][2], bfr[fp][3],
                    s2u(&Bs[(wn + fp * 16 + (lane & 15)) * SCS +
                            kk * 16 + (lane >> 4) * 8]));
#pragma unroll
        for (int fm = 0; fm < 4; ++fm)
#pragma unroll
            for (int fn = 0; fn < 4; ++fn)
                mma16816(acc[fm][fn], afr[fm],
                         bfr[fn >> 1][fn & 1], bfr[fn >> 1][2 + (fn & 1)]);
    }

    uint32_t hs[4][4][2];
    __half* Srow = g_S16 + (size_t)b * NPIX * NPIX;
#pragma unroll
    for (int fm = 0; fm < 4; ++fm) {
        int r0 = n0 + wm + fm * 16 + (lane >> 2);
#pragma unroll
        for (int fn = 0; fn < 4; ++fn) {
            int c = m0 + wn + fn * 8 + (lane & 3) * 2;
            __half2 h0 = __floats2half2_rn(acc[fm][fn][0], acc[fm][fn][1]);
            __half2 h1 = __floats2half2_rn(acc[fm][fn][2], acc[fm][fn][3]);
            hs[fm][fn][0] = *(uint32_t*)&h0;
            hs[fm][fn][1] = *(uint32_t*)&h1;
            *(__half2*)&Srow[(size_t)r0 * NPIX + c] = h0;
            *(__half2*)&Srow[(size_t)(r0 + 8) * NPIX + c] = h1;
        }
    }

    float lv[8];
#pragma unroll
    for (int fn = 0; fn < 4; ++fn)
#pragma unroll
        for (int q = 0; q < 2; ++q) {
            float mv = -3.4e38f;
#pragma unroll
            for (int fm = 0; fm < 4; ++fm) {
                mv = fmaxf(mv, acc[fm][fn][q]);
                mv = fmaxf(mv, acc[fm][fn][q + 2]);
            }
            lv[fn * 2 + q] = mv;
        }
#pragma unroll
    for (int d = 4; d < 32; d <<= 1)
#pragma unroll
        for (int j = 0; j < 8; ++j)
            lv[j] = fmaxf(lv[j], __shfl_xor_sync(0xffffffffu, lv[j], d));
    __syncthreads();
    float* red = (float*)sm;
    float* cmx = (float*)sm + 256;
    if (lane < 4)
#pragma unroll
        for (int j = 0; j < 8; ++j)
            red[(wid & 1) * 128 + wn + (j >> 1) * 8 + (lane & 3) * 2 + (j & 1)] = lv[j];
    __syncthreads();
    if (t < 128) cmx[t] = fmaxf(red[t], red[128 + t]);
    __syncthreads();

    float sums[8] = {0.f, 0.f, 0.f, 0.f, 0.f, 0.f, 0.f, 0.f};
    __half2 l2 = __float2half2_rn(L2E);
#pragma unroll
    for (int fn = 0; fn < 4; ++fn) {
        int c0 = wn + fn * 8 + (lane & 3) * 2;
        __half2 nc2 = __floats2half2_rn(-cmx[c0] * L2E, -cmx[c0 + 1] * L2E);
#pragma unroll
        for (int fm = 0; fm < 4; ++fm)
#pragma unroll
            for (int h = 0; h < 2; ++h) {
                __half2 v = *(__half2*)&hs[fm][fn][h];
                __half2 a2 = __hfma2(v, l2, nc2);
                uint32_t p = h2ex2(*(uint32_t*)&a2);
                float2 f = __half22float2(*(__half2*)&p);
                sums[fn * 2]     += f.x;
                sums[fn * 2 + 1] += f.y;
            }
    }
#pragma unroll
    for (int d = 4; d < 32; d <<= 1)
#pragma unroll
        for (int j = 0; j < 8; ++j)
            sums[j] += __shfl_xor_sync(0xffffffffu, sums[j], d);
    __syncthreads();
    if (lane < 4)
#pragma unroll
        for (int j = 0; j < 8; ++j)
            red[(wid & 1) * 128 + wn + (j >> 1) * 8 + (lane & 3) * 2 + (j & 1)] = sums[j];
    __syncthreads();
    if (t < 128) {
        int base = (b * 32 + blockIdx.y) * NPIX + m0 + t;
        g_pmax[base] = cmx[t];
        g_psum[base] = red[t] + red[128 + t];
    }
}

__global__ void k_combine32() {
    int idx = blockIdx.x * 256 + threadIdx.x;
    int b = idx >> 12, m = idx & 4095;
    float M = -3.4e38f;
#pragma unroll
    for (int c = 0; c < 32; ++c)
        M = fmaxf(M, g_pmax[(b * 32 + c) * NPIX + m]);
    float s = 0.f;
#pragma unroll
    for (int c = 0; c < 32; ++c)
        s += g_psum[(b * 32 + c) * NPIX + m] *
             __expf(g_pmax[(b * 32 + c) * NPIX + m] - M);
    g_nA[idx] = __float2half(-M * L2E);
    g_ci[idx] = __float2half(1.f / s);
}

// ===================== attn_g: M-tile 64, on-the-fly fp16 P ================
#define AGS 72
#define AG_SMEM ((64 + 2 * 128) * AGS * 2)

__global__ __launch_bounds__(256, 2)
void k_attng16() {
    extern __shared__ __half sm[];
    __half* As = sm;                               // 64 x AGS
    __half* BsA[2] = {sm + 64 * AGS, sm + (64 + 128) * AGS};
    int b = blockIdx.z, bm = blockIdx.x * 64;
    int t = threadIdx.x, lane = t & 31, wid = t >> 5;
    int wm = (wid & 1) * 32, wn = (wid >> 1) * 32;
    int r4 = t >> 3, s8 = t & 7;
    const __half* Sb = g_S16 + (size_t)b * NPIX * NPIX;
    const __half* Bg = g_gh + (size_t)b * HIDD * NPIX;
    const __half* nA = g_nA + b * NPIX;
    const __half* ci = g_ci + b * NPIX;
    __half* Cc = g_agt + (size_t)b * NPIX * HIDD;
    ACC_ZERO(2);

    uint4 sv[2];
#pragma unroll
    for (int i = 0; i < 2; ++i)
        sv[i] = *(const uint4*)&Sb[(size_t)(bm + r4 + i * 32) * NPIX + s8 * 8];
#pragma unroll
    for (int i = 0; i < 4; ++i)
        CP16(s2u(&BsA[0][(r4 + i * 32) * AGS + s8 * 8]),
             Bg + (size_t)(r4 + i * 32) * NPIX + s8 * 8);
    CP_COMMIT();

    const __half2 l2 = __float2half2_rn(L2E);
#pragma unroll 1
    for (int ki = 0; ki < 64; ++ki) {
        int m0 = ki * 64;
        if (ki < 63) {
#pragma unroll
            for (int i = 0; i < 4; ++i)
                CP16(s2u(&BsA[(ki + 1) & 1][(r4 + i * 32) * AGS + s8 * 8]),
                     Bg + (size_t)(r4 + i * 32) * NPIX + m0 + 64 + s8 * 8);
            CP_COMMIT();
        }
        union { uint4 v; __half2 h[4]; } ua, uc;
        ua.v = *(const uint4*)&nA[m0 + s8 * 8];
        uc.v = *(const uint4*)&ci[m0 + s8 * 8];
#pragma unroll
        for (int i = 0; i < 2; ++i) {
            union { uint4 v; __half2 h[4]; } u, o;
            u.v = sv[i];
#pragma unroll
            for (int j = 0; j < 4; ++j) {
                __half2 a2 = __hfma2(u.h[j], l2, ua.h[j]);
                uint32_t p = h2ex2(*(uint32_t*)&a2);
                o.h[j] = __hmul2(*(__half2*)&p, uc.h[j]);
            }
            *(uint4*)&As[(r4 + i * 32) * AGS + s8 * 8] = o.v;
        }
        if (ki < 63) {
#pragma unroll
            for (int i = 0; i < 2; ++i)
                sv[i] = *(const uint4*)&Sb[(size_t)(bm + r4 + i * 32) * NPIX +
                                           m0 + 64 + s8 * 8];
        }
        if (ki < 63) CP_WAIT1(); else CP_WAIT0();
        __syncthreads();
        const __half* bs = BsA[ki & 1];
#pragma unroll
        for (int kk = 0; kk < 4; ++kk) {
            uint32_t afr[2][4], bfr[2][4];
#pragma unroll
            for (int fm = 0; fm < 2; ++fm)
                ldsm_x4(afr[fm][0], afr[fm][1], afr[fm][2], afr[fm][3],
                        s2u(&As[(wm + fm * 16 + (lane & 15)) * AGS +
                                kk * 16 + (lane >> 4) * 8]));
#pragma unroll
            for (int fp = 0; fp < 2; ++fp)
                ldsm_x4(bfr[fp][0], bfr[fp][1], bfr[fp][2], bfr[fp][3],
                        s2u(&bs[(wn + fp * 16 + (lane & 15)) * AGS +
                                kk * 16 + (lane >> 4) * 8]));
#pragma unroll
            for (int fm = 0; fm < 2; ++fm)
#pragma unroll
                for (int fn = 0; fn < 4; ++fn)
                    mma16816(acc[fm][fn], afr[fm],
                             bfr[fn >> 1][fn & 1], bfr[fn >> 1][2 + (fn & 1)]);
        }
        __syncthreads();
    }
#pragma unroll
    for (int fm = 0; fm < 2; ++fm) {
        int r0 = bm + wm + fm * 16 + (lane >> 2);
#pragma unroll
        for (int fn = 0; fn < 4; ++fn) {
            int c = wn + fn * 8 + (lane & 3) * 2;
            *(__half2*)&Cc[(size_t)r0 * HIDD + c] =
                __floats2half2_rn(acc[fm][fn][0], acc[fm][fn][1]);
            *(__half2*)&Cc[(size_t)(r0 + 8) * HIDD + c] =
                __floats2half2_rn(acc[fm][fn][2], acc[fm][fn][3]);
        }
    }
}

// ===================== mask GEMM + residual ================================
__global__ __launch_bounds__(256, 2)
void k_mask16(const float* __restrict__ x, float* __restrict__ out) {
    __shared__ __half As[2][128 * SMS];
    __shared__ __half Bs[2][128 * SMS];
    int bm = blockIdx.y * 128, bn = blockIdx.x * 128, b = blockIdx.z;
    const __half* A = g_whm;
    const __half* B = g_agt + (size_t)b * NPIX * HIDD;
    int t = threadIdx.x, lane = t & 31, wid = t >> 5;
    int wm = (wid & 1) * 64, wn = (wid >> 1) * 32;
    ACC_ZERO(4);
    const int nk = HIDD / 32;
#pragma unroll 1
    for (int ki = -1; ki < nk; ++ki) {
        int kl = ki + 1;
        if (kl < nk) {
#pragma unroll
            for (int i = 0; i < 2; ++i) {
                int e = t + i * 256, r = e >> 2, s = e & 3;
                CP16(s2u(&As[kl & 1][r * SMS + s * 8]),
                     A + (size_t)(bm + r) * HIDD + kl * 32 + s * 8);
                CP16(s2u(&Bs[kl & 1][r * SMS + s * 8]),
                     B + (size_t)(bn + r) * HIDD + kl * 32 + s * 8);
            }
            CP_COMMIT();
        }
        if (ki < 0) continue;
        if (kl < nk) CP_WAIT1(); else CP_WAIT0();
        __syncthreads();
        const __half* as = As[ki & 1];
        const __half* bs = Bs[ki & 1];
        MMA_CHUNK(as, bs);
        __syncthreads();
    }
#pragma unroll
    for (int fm = 0; fm < 4; ++fm) {
        int r0 = bm + wm + fm * 16 + (lane >> 2);
#pragma unroll
        for (int fn = 0; fn < 4; ++fn) {
            int c = bn + wn + fn * 8 + (lane & 3) * 2;
            size_t o0 = (size_t)b * CCH * NPIX + (size_t)r0 * NPIX + c;
            size_t o1 = o0 + 8ull * NPIX;
            float2 x0 = *(const float2*)&x[o0];
            float2 x1 = *(const float2*)&x[o1];
            *(float2*)&out[o0] = make_float2(acc[fm][fn][0] + x0.x,
                                             acc[fm][fn][1] + x0.y);
            *(float2*)&out[o1] = make_float2(acc[fm][fn][2] + x1.x,
                                             acc[fm][fn][3] + x1.y);
        }
    }
}

// ===================== prep kernels ========================================
__global__ void k_wconv4(const float* __restrict__ a, const float* __restrict__ b,
                         const float* __restrict__ c, const float* __restrict__ d) {
    int i = blockIdx.x * 256 + threadIdx.x;
    int w = i >> 15, j = i & 32767;
    const float* src = w == 0 ? a : (w == 1 ? b : (w == 2 ? c : d));
    __half* dst = w == 0 ? g_whp : (w == 1 ? g_wht : (w == 2 ? g_whg : g_whm));
    dst[j] = __float2half(src[j]);
}

__global__ void k_xtrans(const float* __restrict__ x) {
    __shared__ float tile[32][33];
    int b = blockIdx.z;
    int n0 = blockIdx.x * 32, c0 = blockIdx.y * 32;
    const float* xb = x + (size_t)b * CCH * NPIX;
    __half* ob = g_xt + (size_t)b * NPIX * CCH;
    int tx = threadIdx.x, ty = threadIdx.y;
#pragma unroll
    for (int i = 0; i < 32; i += 8)
        tile[ty + i][tx] = xb[(size_t)(c0 + ty + i) * NPIX + n0 + tx];
    __syncthreads();
#pragma unroll
    for (int i = 0; i < 32; i += 8)
        ob[(size_t)(n0 + ty + i) * CCH + c0 + tx] = __float2half(tile[tx][ty + i]);
}

// ===================== launcher ============================================
extern "C" void kernel_launch(void* const* d_in, const int* in_sizes, int n_in,
                              void* d_out, int out_size) {
    const float* x       = (const float*)d_in[0];
    const float* w_phi   = (const float*)d_in[1];
    const float* w_theta = (const float*)d_in[2];
    const float* w_g     = (const float*)d_in[3];
    const float* w_mask  = (const float*)d_in[4];
    float* out = (float*)d_out;
    (void)in_sizes; (void)n_in; (void)out_size;

    static int attr_done = 0;
    if (!attr_done) {
        cudaFuncSetAttribute(k_scores16, cudaFuncAttributeMaxDynamicSharedMemorySize,
                             SC_SMEM);
        cudaFuncSetAttribute(k_attng16, cudaFuncAttributeMaxDynamicSharedMemorySize,
                             AG_SMEM);
        attr_done = 1;
    }

    __half *whg, *xt, *gh;
    cudaGetSymbolAddress((void**)&whg, g_whg);
    cudaGetSymbolAddress((void**)&xt,  g_xt);
    cudaGetSymbolAddress((void**)&gh,  g_gh);

    k_wconv4<<<512, 256>>>(w_phi, w_theta, w_g, w_mask);
    k_xtrans<<<dim3(NPIX / 32, CCH / 32, BSZ), dim3(32, 8)>>>(x);

    const long long sX = (long long)NPIX * CCH;
    const long long sH = (long long)NPIX * HIDD;

    k_qkvPT<<<dim3(2, 32, BSZ), 256>>>();
    // g[c][m]: A = W_g (rows c, K=256), B = x^T (rows m, K-major c)
    k_gemm16_64<<<dim3(NPIX / 128, HIDD / 64, BSZ), 256>>>(
        whg, xt, gh, 0, sX, sH, CCH, CCH, NPIX, CCH);
    k_scores16<<<dim3(32, 32, BSZ), 256, SC_SMEM>>>();
    k_combine32<<<dim3(BSZ * NPIX / 256), 256>>>();
    k_attng16<<<dim3(NPIX / 64, 1, BSZ), 256, AG_SMEM>>>();
    k_mask16<<<dim3(NPIX / 128, CCH / 128, BSZ), 256>>>(x, out);
}